// round 8
// baseline (speedup 1.0000x reference)
#include <cuda_runtime.h>
#include <math.h>

// Quaternion LSTM: T=128, B=64, F=512, H=1024.
// Round 8: recurrence via 12-mult quaternion Karatsuba (FLOPs x0.75) +
// dynamic tile stealing (fixes 256-CTA/148-SM imbalance). Persistent kernel,
// 2 barriers/step. Input/output projections unchanged (dense, passed R7).

#define T_ 128
#define B_ 64
#define Fdim 512
#define H_ 1024
#define N4 (4 * H_)          // 4096
#define FO (Fdim + 1)        // 513
#define NCTA 296             // 148 SMs x 2
#define NTILES 768           // 2 ksplit x 6 combos x 64 ncol-tiles

// ---- scratch (static device globals: allocation-free) ----
__device__ float g_Wcat[(size_t)Fdim * N4];            //  8 MB
__device__ float g_bias4[N4];
__device__ float g_Uq[6 * 256 * 2048];                 // 12.6 MB combined U
__device__ float g_G[(size_t)T_ * B_ * N4];            // 128 MB (pre-gates)
__device__ float g_m[2 * 6 * B_ * 2048];               // 6.3 MB (12-mult partials)
__device__ float g_h[B_ * H_];
__device__ float g_c[B_ * H_];
__device__ float g_Hbuf[(size_t)T_ * B_ * H_];         // 32 MB
__device__ unsigned g_ctr[T_];                         // per-step tile counters
__device__ unsigned g_cnt;
__device__ volatile unsigned g_gen;

__device__ const float c_sgn[16] = {
    1.f, -1.f, -1.f, -1.f,
    1.f,  1.f, -1.f,  1.f,
    1.f,  1.f,  1.f, -1.f,
    1.f, -1.f,  1.f,  1.f
};

// ---------------- init ----------------
__global__ void init_state() {
    int idx = blockIdx.x * blockDim.x + threadIdx.x;
    if (idx < B_ * H_) { g_h[idx] = 0.f; g_c[idx] = 0.f; }
    if (idx < T_) g_ctr[idx] = 0;
    if (idx == 0) { g_cnt = 0; g_gen = 0; }
}

// ---------------- builds ----------------
__global__ void build_W(const float* __restrict__ wf, const float* __restrict__ wi,
                        const float* __restrict__ wo, const float* __restrict__ wc) {
    int idx = blockIdx.x * blockDim.x + threadIdx.x;
    if (idx >= Fdim * N4) return;
    int row  = idx / N4;
    int col  = idx % N4;
    int gate = col / H_;
    int cj   = col % H_;
    int rb = row / (Fdim / 4), a = row % (Fdim / 4);
    int cb = cj / (H_ / 4),    b = cj % (H_ / 4);
    const float* w = (gate == 0) ? wf : (gate == 1) ? wi : (gate == 2) ? wo : wc;
    g_Wcat[idx] = c_sgn[cb * 4 + rb] *
                  w[((size_t)(rb ^ cb) * (Fdim / 4) + a) * (H_ / 4) + b];
}

// Combined U for the 12-mult scheme. u layout: (4 comp, 256, 256).
// combo c -> (p0, p1) weights:
//  c0: u0 , u2     c1: u1 , u3     c2: u0+u1 , u3-u2
//  c3: u2 , u0     c4: u3 , u1     c5: u3-u2 , u0+u1
__global__ void build_Uq(const float* __restrict__ uf, const float* __restrict__ ui,
                         const float* __restrict__ uo, const float* __restrict__ uc) {
    int idx = blockIdx.x * blockDim.x + threadIdx.x;
    if (idx >= 6 * 256 * 2048) return;
    int c   = idx / (256 * 2048);
    int rem = idx % (256 * 2048);
    int k   = rem / 2048;
    int col = rem % 2048;
    int g   = col >> 9;
    int p   = (col >> 8) & 1;
    int n4  = col & 255;
    const float* u = (g == 0) ? uf : (g == 1) ? ui : (g == 2) ? uo : uc;
    size_t base = (size_t)k * 256 + n4;           // u[comp] offset = comp*65536
    float u0 = u[base], u1 = u[base + 65536], u2 = u[base + 131072], u3 = u[base + 196608];
    float v;
    if (c == 0) v = p ? u2 : u0;
    else if (c == 1) v = p ? u3 : u1;
    else if (c == 2) v = p ? (u3 - u2) : (u0 + u1);
    else if (c == 3) v = p ? u0 : u2;
    else if (c == 4) v = p ? u1 : u3;
    else             v = p ? (u0 + u1) : (u3 - u2);
    g_Uq[idx] = v;
}

__global__ void build_bias(const float* __restrict__ bf, const float* __restrict__ bi,
                           const float* __restrict__ bo, const float* __restrict__ bc) {
    int idx = blockIdx.x * blockDim.x + threadIdx.x;
    if (idx >= N4) return;
    int gate = idx / H_, j = idx % H_;
    const float* b = (gate == 0) ? bf : (gate == 1) ? bi : (gate == 2) ? bo : bc;
    g_bias4[idx] = b[j];
}

// ---------------- generic fp32 GEMM (unchanged, passed R7) ----------------
__device__ __forceinline__ void gemm_body(const float* __restrict__ A,
                                          const float* __restrict__ Bm,
                                          const float* __restrict__ bias,
                                          float* __restrict__ C,
                                          int M, int N, int K) {
    const int BM = 128, BN = 128, BK = 16;
    __shared__ float As[BK][BM];
    __shared__ float Bs[BK][BN];
    int tid = threadIdx.x;
    int tx = tid % 16, ty = tid / 16;
    int rowBase = blockIdx.y * BM;
    int colBase = blockIdx.x * BN;
    float acc[8][8];
    #pragma unroll
    for (int i = 0; i < 8; i++)
        #pragma unroll
        for (int j = 0; j < 8; j++) acc[i][j] = 0.f;

    for (int k0 = 0; k0 < K; k0 += BK) {
        #pragma unroll
        for (int i = 0; i < 2; i++) {
            int lin = tid + i * 256;
            int r = lin >> 2, c4 = (lin & 3) * 4;
            float4 v = *reinterpret_cast<const float4*>(
                &A[(size_t)(rowBase + r) * K + k0 + c4]);
            As[c4 + 0][r] = v.x;
            As[c4 + 1][r] = v.y;
            As[c4 + 2][r] = v.z;
            As[c4 + 3][r] = v.w;
        }
        #pragma unroll
        for (int i = 0; i < 8; i++) {
            int lin = tid + i * 256;
            int kk = lin >> 7, n = lin & 127;
            int gn = colBase + n;
            float v = 0.f;
            if (gn < N) v = Bm[(size_t)(k0 + kk) * N + gn];
            Bs[kk][n] = v;
        }
        __syncthreads();
        #pragma unroll
        for (int kk = 0; kk < BK; kk++) {
            float a[8], b[8];
            float4 a0 = *reinterpret_cast<const float4*>(&As[kk][ty * 8]);
            float4 a1 = *reinterpret_cast<const float4*>(&As[kk][ty * 8 + 4]);
            float4 b0 = *reinterpret_cast<const float4*>(&Bs[kk][tx * 8]);
            float4 b1 = *reinterpret_cast<const float4*>(&Bs[kk][tx * 8 + 4]);
            a[0]=a0.x; a[1]=a0.y; a[2]=a0.z; a[3]=a0.w;
            a[4]=a1.x; a[5]=a1.y; a[6]=a1.z; a[7]=a1.w;
            b[0]=b0.x; b[1]=b0.y; b[2]=b0.z; b[3]=b0.w;
            b[4]=b1.x; b[5]=b1.y; b[6]=b1.z; b[7]=b1.w;
            #pragma unroll
            for (int i = 0; i < 8; i++)
                #pragma unroll
                for (int j = 0; j < 8; j++)
                    acc[i][j] += a[i] * b[j];
        }
        __syncthreads();
    }
    #pragma unroll
    for (int i = 0; i < 8; i++) {
        int gm = rowBase + ty * 8 + i;
        if (gm >= M) continue;
        #pragma unroll
        for (int j = 0; j < 8; j++) {
            int gn = colBase + tx * 8 + j;
            if (gn >= N) continue;
            float v = acc[i][j];
            if (bias) v += bias[gn];
            C[(size_t)gm * N + gn] = v;
        }
    }
}

__global__ __launch_bounds__(256) void gemm_in(const float* __restrict__ x) {
    gemm_body(x, g_Wcat, g_bias4, g_G, T_ * B_, N4, Fdim);
}
__global__ __launch_bounds__(256) void gemm_out(const float* __restrict__ fw,
                                                const float* __restrict__ fb,
                                                float* __restrict__ out) {
    gemm_body(g_Hbuf, fw, fb, out, T_ * B_, FO, H_);
}

// ---------------- grid barrier ----------------
__device__ __forceinline__ void grid_barrier() {
    __syncthreads();
    __threadfence();
    if (threadIdx.x == 0) {
        unsigned gen = g_gen;
        unsigned prev = atomicAdd(&g_cnt, 1u);
        if (prev == NCTA - 1) {
            g_cnt = 0;
            __threadfence();
            g_gen = gen + 1;
        } else {
            while (g_gen == gen) { }
        }
    }
    __syncthreads();
    __threadfence();
}

// ---------------- persistent recurrence ----------------
// Phase 1: 768 tiles (64x32x128) of the 6-combo batched GEMM, dynamic stealing.
// Phase 2: Karatsuba combine + gates + state update (4096 threads).
__global__ __launch_bounds__(256, 2) void recurrence() {
    __shared__ float As[32][68];
    __shared__ float Bs[32][36];
    __shared__ unsigned s_tile;
    int tid = threadIdx.x;
    int tx = tid & 15, ty = tid >> 4;       // micro: 4 rows x 2 cols
    const float4* h4 = reinterpret_cast<const float4*>(g_h);
    int gtid = blockIdx.x * 256 + tid;

    for (int t = 0; t < T_; t++) {
        // ======== phase 1: m[s][c] = A_c[:, ksplit s] @ Uq_c, tiles stolen
        for (;;) {
            if (tid == 0) s_tile = atomicAdd(&g_ctr[t], 1u);
            __syncthreads();
            unsigned tl = s_tile;
            __syncthreads();
            if (tl >= NTILES) break;
            int s    = tl & 1;
            int rest = tl >> 1;
            int c    = rest % 6;
            int ncol = rest / 6;            // 0..63, 32-wide col tiles
            int kbase = s * 128;
            int base1 = (c == 0 || c == 2) ? 0 : (c == 1) ? 256
                      : (c == 3 || c == 5) ? 512 : 768;
            int base2 = (c == 2) ? 256 : (c == 5) ? 768 : -1;

            float acc[4][2];
            #pragma unroll
            for (int i = 0; i < 4; i++) { acc[i][0] = 0.f; acc[i][1] = 0.f; }

            for (int k0 = 0; k0 < 128; k0 += 32) {
                // A: 64 rows x 32 k (combo formed on the fly), transposed store
                #pragma unroll
                for (int i = 0; i < 2; i++) {
                    int lin = tid + i * 256;
                    int r = lin >> 3, kq = (lin & 7) * 4;
                    int off = base1 + kbase + k0 + kq;
                    float4 v = h4[(r * H_ + off) >> 2];
                    if (base2 >= 0) {
                        float4 w = h4[(r * H_ + off + (base2 - base1)) >> 2];
                        v.x += w.x; v.y += w.y; v.z += w.z; v.w += w.w;
                    }
                    As[kq + 0][r] = v.x;
                    As[kq + 1][r] = v.y;
                    As[kq + 2][r] = v.z;
                    As[kq + 3][r] = v.w;
                }
                {   // B: 32 k x 32 cols from g_Uq
                    int r = tid >> 3, cq = (tid & 7) * 4;
                    float4 v = *reinterpret_cast<const float4*>(
                        &g_Uq[((size_t)c * 256 + kbase + k0 + r) * 2048 + ncol * 32 + cq]);
                    *reinterpret_cast<float4*>(&Bs[r][cq]) = v;
                }
                __syncthreads();
                #pragma unroll
                for (int kk = 0; kk < 32; kk++) {
                    float4 a = *reinterpret_cast<const float4*>(&As[kk][ty * 4]);
                    float2 b = *reinterpret_cast<const float2*>(&Bs[kk][tx * 2]);
                    acc[0][0] += a.x * b.x; acc[0][1] += a.x * b.y;
                    acc[1][0] += a.y * b.x; acc[1][1] += a.y * b.y;
                    acc[2][0] += a.z * b.x; acc[2][1] += a.z * b.y;
                    acc[3][0] += a.w * b.x; acc[3][1] += a.w * b.y;
                }
                __syncthreads();
            }
            float* mout = g_m + ((size_t)(s * 6 + c) * B_) * 2048;
            #pragma unroll
            for (int i = 0; i < 4; i++) {
                int row = ty * 4 + i;
                float2 v = {acc[i][0], acc[i][1]};
                *reinterpret_cast<float2*>(&mout[(size_t)row * 2048 + ncol * 32 + tx * 2]) = v;
            }
        }

        grid_barrier();

        // ======== phase 2: combine + update. thread = (b, n4-quad), 4096 total
        if (gtid < 4096) {
            int b   = gtid >> 6;
            int n4q = (gtid & 63) * 4;      // n4 base (0..252)
            const float4* m4 = reinterpret_cast<const float4*>(g_m);
            const float4* G4 = reinterpret_cast<const float4*>(
                g_G + (size_t)((size_t)t * B_ + b) * N4);
            // M(c,p,g) as float4 over n4: index ((s*6+c)*64 + b)*512 + (g*2+p)*64 + n4q/4
            #define MM(c, p, g) ({                                              \
                float4 _a = m4[((size_t)((0 * 6 + (c)) * B_ + b)) * 512 + ((g) * 2 + (p)) * 64 + (n4q >> 2)]; \
                float4 _b = m4[((size_t)((1 * 6 + (c)) * B_ + b)) * 512 + ((g) * 2 + (p)) * 64 + (n4q >> 2)]; \
                make_float4(_a.x + _b.x, _a.y + _b.y, _a.z + _b.z, _a.w + _b.w); })
            #pragma unroll
            for (int o = 0; o < 4; o++) {
                float4 pre[4];
                #pragma unroll
                for (int g = 0; g < 4; g++) {
                    float4 r = G4[g * 256 + o * 64 + (n4q >> 2)];
                    float4 q;
                    if (o == 0) {            // M00 - M10 - M30 - M40
                        float4 a = MM(0,0,g), b2 = MM(1,0,g), c2 = MM(3,0,g), d = MM(4,0,g);
                        q.x = a.x - b2.x - c2.x - d.x; q.y = a.y - b2.y - c2.y - d.y;
                        q.z = a.z - b2.z - c2.z - d.z; q.w = a.w - b2.w - c2.w - d.w;
                    } else if (o == 1) {     // M20 - M00 - M10 - M50 - M30 + M40
                        float4 a = MM(2,0,g), b2 = MM(0,0,g), c2 = MM(1,0,g),
                               d = MM(5,0,g), e = MM(3,0,g), f = MM(4,0,g);
                        q.x = a.x - b2.x - c2.x - d.x - e.x + f.x;
                        q.y = a.y - b2.y - c2.y - d.y - e.y + f.y;
                        q.z = a.z - b2.z - c2.z - d.z - e.z + f.z;
                        q.w = a.w - b2.w - c2.w - d.w - e.w + f.w;
                    } else if (o == 2) {     // M31 - M41 + M01 + M11
                        float4 a = MM(3,1,g), b2 = MM(4,1,g), c2 = MM(0,1,g), d = MM(1,1,g);
                        q.x = a.x - b2.x + c2.x + d.x; q.y = a.y - b2.y + c2.y + d.y;
                        q.z = a.z - b2.z + c2.z + d.z; q.w = a.w - b2.w + c2.w + d.w;
                    } else {                 // M51 - M31 - M41 + M21 + M01 - M11
                        float4 a = MM(5,1,g), b2 = MM(3,1,g), c2 = MM(4,1,g),
                               d = MM(2,1,g), e = MM(0,1,g), f = MM(1,1,g);
                        q.x = a.x - b2.x - c2.x + d.x + e.x - f.x;
                        q.y = a.y - b2.y - c2.y + d.y + e.y - f.y;
                        q.z = a.z - b2.z - c2.z + d.z + e.z - f.z;
                        q.w = a.w - b2.w - c2.w + d.w + e.w - f.w;
                    }
                    pre[g] = make_float4(r.x + q.x, r.y + q.y, r.z + q.z, r.w + q.w);
                }
                size_t col = (size_t)b * H_ + o * 256 + n4q;
                float4 cprev = *reinterpret_cast<const float4*>(&g_c[col]);
                float fv[4] = {pre[0].x, pre[0].y, pre[0].z, pre[0].w};
                float iv[4] = {pre[1].x, pre[1].y, pre[1].z, pre[1].w};
                float ov[4] = {pre[2].x, pre[2].y, pre[2].z, pre[2].w};
                float av[4] = {pre[3].x, pre[3].y, pre[3].z, pre[3].w};
                float cp[4] = {cprev.x, cprev.y, cprev.z, cprev.w};
                float cnv[4], hnv[4];
                #pragma unroll
                for (int q2 = 0; q2 < 4; q2++) {
                    float ff = 1.f / (1.f + expf(-fv[q2]));
                    float ii = 1.f / (1.f + expf(-iv[q2]));
                    float oo = 1.f / (1.f + expf(-ov[q2]));
                    float cc = ii * tanhf(av[q2]) + ff * cp[q2];
                    cnv[q2] = cc;
                    hnv[q2] = oo * tanhf(cc);
                }
                float4 cn = {cnv[0], cnv[1], cnv[2], cnv[3]};
                float4 hn = {hnv[0], hnv[1], hnv[2], hnv[3]};
                *reinterpret_cast<float4*>(&g_c[col]) = cn;
                *reinterpret_cast<float4*>(&g_h[col]) = hn;
                *reinterpret_cast<float4*>(&g_Hbuf[(size_t)t * B_ * H_ + col]) = hn;
            }
            #undef MM
        }

        grid_barrier();
    }
}

// ---------------- launch ----------------
extern "C" void kernel_launch(void* const* d_in, const int* in_sizes, int n_in,
                              void* d_out, int out_size) {
    const float* x    = (const float*)d_in[0];
    const float* wfxw = (const float*)d_in[1];
    const float* wfxb = (const float*)d_in[2];
    const float* wixw = (const float*)d_in[3];
    const float* wixb = (const float*)d_in[4];
    const float* woxw = (const float*)d_in[5];
    const float* woxb = (const float*)d_in[6];
    const float* wcxw = (const float*)d_in[7];
    const float* wcxb = (const float*)d_in[8];
    const float* ufhw = (const float*)d_in[9];
    const float* uihw = (const float*)d_in[10];
    const float* uohw = (const float*)d_in[11];
    const float* uchw = (const float*)d_in[12];
    const float* fcow = (const float*)d_in[13];
    const float* fcob = (const float*)d_in[14];
    float* out = (float*)d_out;

    init_state<<<(B_ * H_ + 255) / 256, 256>>>();
    build_W<<<(Fdim * N4 + 255) / 256, 256>>>(wfxw, wixw, woxw, wcxw);
    build_bias<<<(N4 + 255) / 256, 256>>>(wfxb, wixb, woxb, wcxb);
    build_Uq<<<(6 * 256 * 2048 + 255) / 256, 256>>>(ufhw, uihw, uohw, uchw);

    {   // input projections: G = x @ Wcat + bias
        dim3 grid(N4 / 128, (T_ * B_) / 128);
        gemm_in<<<grid, 256>>>(x);
    }

    recurrence<<<NCTA, 256>>>();

    {   // output projection: out = Hbuf @ fco_w + fco_b
        dim3 grid((FO + 127) / 128, (T_ * B_) / 128);
        gemm_out<<<grid, 256>>>(fcow, fcob, out);
    }
}